// round 5
// baseline (speedup 1.0000x reference)
#include <cuda_runtime.h>

#define NS 20480
#define EMAX 120000
#define TMAX 2097152
#define DHIST 16384
#define NT2 512            /* TMAX/4096 compaction tiles */

__device__ __align__(16) int g_srcHist[NS + 8], g_tgtHist[NS + 8];
__device__ __align__(16) int g_srcBase[NS + 8], g_tgtBase[NS + 8];
__device__ int g_curA[NS + 8], g_curB[NS + 8], g_curC[NS + 8];
__device__ int g_eScat[EMAX], g_ePerm[EMAX];
__device__ int g_srcS[EMAX], g_tgtS[EMAX];
__device__ int g_oScat[EMAX], g_order[EMAX];
__device__ __align__(16) int g_prod[NS + 8], g_prefixG[NS + 8];
__device__ int g_tri0[TMAX], g_tri1[TMAX], g_tri2[TMAX];
__device__ __align__(16) int g_triS0[TMAX], g_triS1[TMAX], g_triS2[TMAX];
__device__ int g_tScat[TMAX], g_tPerm[TMAX];
__device__ __align__(16) int g_histTri[NS + 8];
__device__ int g_triBase[NS + 8];
__device__ int g_deg[NS + 8];
__device__ __align__(16) int g_histD[DHIST + 8];
__device__ int g_cumD[DHIST + 8];
__device__ int g_maxNode, g_P;
__device__ __align__(16) int g_tieEx[NS + 8];
__device__ int g_keep[NS + 8];
__device__ __align__(16) int g_srcPresent[NS + 8], g_present[NS + 8];
__device__ int g_srcRank[NS + 8], g_rank[NS + 8];
__device__ int g_segHead[NS + 8];
__device__ float g_Wt[3 * 64 * 64];
__device__ int g_tileSum[NT2 + 8], g_tileOff[NT2 + 8];
__device__ unsigned long long g_barCount, g_barPhase;

// ---------------- grid barrier (all blocks resident; deterministic) --------
__device__ __forceinline__ void gridBar(unsigned long long ep, int nb) {
    __syncthreads();
    if (threadIdx.x == 0) {
        __threadfence();
        unsigned long long old = atomicAdd(&g_barCount, 1ull);
        if (old == (unsigned long long)(nb - 1)) {
            g_barCount = 0ull;
            __threadfence();
            atomicExch(&g_barPhase, ep);
        } else {
            while (*(volatile unsigned long long*)&g_barPhase < ep) __nanosleep(64);
        }
        __threadfence();
    }
    __syncthreads();
}

// ---------------- block exclusive scan -------------------------------------
__device__ __forceinline__ int blockScanEx(int v, int* tot) {
    __shared__ int s_w[32];
    __shared__ int s_tot;
    int lane = threadIdx.x & 31, wid = threadIdx.x >> 5, nw = blockDim.x >> 5;
    int inc = v;
#pragma unroll
    for (int o = 1; o < 32; o <<= 1) {
        int u = __shfl_up_sync(0xffffffffu, inc, o);
        if (lane >= o) inc += u;
    }
    if (lane == 31) s_w[wid] = inc;
    __syncthreads();
    if (wid == 0) {
        int sv = (lane < nw) ? s_w[lane] : 0;
        int si = sv;
#pragma unroll
        for (int o = 1; o < 32; o <<= 1) {
            int u = __shfl_up_sync(0xffffffffu, si, o);
            if (lane >= o) si += u;
        }
        s_w[lane] = si - sv;
        if (lane == 31) s_tot = si;
    }
    __syncthreads();
    int ex = inc - v + s_w[wid];
    *tot = s_tot;
    __syncthreads();
    return ex;
}

template <int VPT4>
__device__ void sbScanFast(const int* in, int* out, int n) {
    int v[VPT4 * 4];
    const int4* in4 = (const int4*)in;
#pragma unroll
    for (int j = 0; j < VPT4; j++) {
        int4 q = in4[threadIdx.x * VPT4 + j];
        v[4 * j] = q.x; v[4 * j + 1] = q.y; v[4 * j + 2] = q.z; v[4 * j + 3] = q.w;
    }
    int loc = 0;
#pragma unroll
    for (int j = 0; j < VPT4 * 4; j++) { int t = v[j]; v[j] = loc; loc += t; }
    int tot, ex = blockScanEx(loc, &tot);
    int base = threadIdx.x * VPT4 * 4;
#pragma unroll
    for (int j = 0; j < VPT4 * 4; j++) {
        int i = base + j;
        if (i < n) out[i] = ex + v[j];
    }
    if (threadIdx.x == 0) out[n] = tot;
}

__global__ void kBarInit() { g_barCount = 0ull; g_barPhase = 0ull; }

__global__ void __launch_bounds__(1024, 1) kMega(
    const float* __restrict__ x, const int* __restrict__ ei,
    const float* __restrict__ W, const float* __restrict__ bvec,
    float* __restrict__ out, int N, int E)
{
    __shared__ float sv[32][192];
    __shared__ int s_dstar, s_r;
    const int tid = threadIdx.x, bid = blockIdx.x, nb = gridDim.x;
    const int gsz = nb * 1024;
    const int g0 = bid * 1024 + tid;
    const int warpId = g0 >> 5, lane = tid & 31, nwarps = nb * 32;
    unsigned long long ep = 0;

    // ph0: init
    for (int i = g0; i < NS; i += gsz) {
        g_srcHist[i] = 0; g_tgtHist[i] = 0; g_histTri[i] = 0;
        g_deg[i] = 0; g_srcPresent[i] = 0; g_present[i] = 0;
        g_curA[i] = 0; g_curB[i] = 0; g_curC[i] = 0;
    }
    for (int i = g0; i < DHIST; i += gsz) g_histD[i] = 0;
    for (int i = g0; i < 12288; i += gsz) {
        int o = i & 63, ii = (i >> 6) & 63, k = i >> 12;
        g_Wt[i] = W[o * 192 + ii * 3 + k];
    }
    if (g0 == 0) g_maxNode = -1;
    gridBar(++ep, nb);

    // ph1: edge histograms
    for (int e = g0; e < E; e += gsz) {
        atomicAdd(&g_srcHist[ei[e]], 1);
        atomicAdd(&g_tgtHist[ei[E + e]], 1);
    }
    gridBar(++ep, nb);

    // ph2: scans (block 0)
    if (bid == 0) {
        for (int i = tid; i < NS; i += 1024)
            g_prod[i] = (i < N) ? g_srcHist[i] * g_tgtHist[i] : 0;
        __syncthreads();
        sbScanFast<5>(g_srcHist, g_srcBase, N);
        sbScanFast<5>(g_tgtHist, g_tgtBase, N);
        sbScanFast<5>(g_prod, g_prefixG, N);
    }
    gridBar(++ep, nb);

    // ph3: scatter by src
    for (int e = g0; e < E; e += gsz) {
        int v = ei[e];
        g_eScat[g_srcBase[v] + atomicAdd(&g_curA[v], 1)] = e;
    }
    gridBar(++ep, nb);

    // ph4: stable rank-sort per src bucket
    for (int w = warpId; w < N; w += nwarps) {
        int lo = g_srcBase[w], s = g_srcBase[w + 1] - lo;
        for (int i = lane; i < s; i += 32) {
            int val = g_eScat[lo + i], r = 0;
            for (int j = 0; j < s; j++) r += (g_eScat[lo + j] < val);
            g_ePerm[lo + r] = val;
        }
        __syncwarp();
        for (int i = lane; i < s; i += 32) {
            int e = g_ePerm[lo + i];
            g_srcS[lo + i] = w;
            g_tgtS[lo + i] = ei[E + e];
        }
        __syncwarp();
    }
    gridBar(++ep, nb);

    // ph5: scatter by tgt
    for (int j = g0; j < E; j += gsz) {
        int w = g_tgtS[j];
        g_oScat[g_tgtBase[w] + atomicAdd(&g_curB[w], 1)] = j;
    }
    gridBar(++ep, nb);

    // ph6: stable rank-sort per tgt bucket -> order
    for (int w = warpId; w < N; w += nwarps) {
        int lo = g_tgtBase[w], s = g_tgtBase[w + 1] - lo;
        for (int i = lane; i < s; i += 32) {
            int val = g_oScat[lo + i], r = 0;
            for (int j = 0; j < s; j++) r += (g_oScat[lo + j] < val);
            g_order[lo + r] = val;
        }
        __syncwarp();
    }
    gridBar(++ep, nb);

    // ph7: generate triplets
    for (int e = g0; e < E; e += gsz) {
        int v = g_srcS[e];
        int lb = g_tgtBase[v];
        int din = g_tgtBase[v + 1] - lb;
        if (din <= 0) continue;
        int t0 = g_prefixG[v] + (e - g_srcBase[v]) * din;
        int w = g_tgtS[e];
        int mx = v > w ? v : w;
        for (int off = 0; off < din; off++) {
            int t = t0 + off;
            if (t >= TMAX) break;
            int a = g_srcS[g_order[lb + off]];
            g_tri0[t] = a; g_tri1[t] = v; g_tri2[t] = w;
            atomicAdd(&g_histTri[a], 1);
            atomicAdd(&g_deg[a], 1);
            if (a > mx) mx = a;
        }
        atomicAdd(&g_deg[v], din);
        atomicAdd(&g_deg[w], din);
        atomicMax(&g_maxNode, mx);
    }
    gridBar(++ep, nb);

    // ph8: scan triplet histogram (block 0)
    if (bid == 0) sbScanFast<5>(g_histTri, g_triBase, N);
    gridBar(++ep, nb);

    int T = g_prefixG[N]; if (T > TMAX) T = TMAX;

    // ph9: scatter triplets by tri0
    for (int t = g0; t < T; t += gsz) {
        int a = g_tri0[t];
        g_tScat[g_triBase[a] + atomicAdd(&g_curC[a], 1)] = t;
    }
    gridBar(++ep, nb);

    // ph10: stable rank-sort per tri0 bucket
    for (int w = warpId; w < N; w += nwarps) {
        int lo = g_triBase[w], s = g_triBase[w + 1] - lo;
        for (int i = lane; i < s; i += 32) {
            int val = g_tScat[lo + i], r = 0;
            for (int j = 0; j < s; j++) r += (g_tScat[lo + j] < val);
            g_tPerm[lo + r] = val;
        }
        __syncwarp();
        for (int i = lane; i < s; i += 32) {
            int t = g_tPerm[lo + i];
            g_triS0[lo + i] = g_tri0[t];
            g_triS1[lo + i] = g_tri1[t];
            g_triS2[lo + i] = g_tri2[t];
        }
        __syncwarp();
    }
    gridBar(++ep, nb);

    // ph11: degree histogram
    {
        int L = g_maxNode + 1;
        for (int i = g0; i < L; i += gsz) {
            int d = g_deg[i];
            if (d > DHIST - 1) d = DHIST - 1;
            atomicAdd(&g_histD[d], 1);
        }
    }
    gridBar(++ep, nb);

    // ph12: median-degree selection + keep mask (block 0)
    if (bid == 0) {
        sbScanFast<4>(g_histD, g_cumD, DHIST);
        __syncthreads();
        int L = g_maxNode + 1, half = L >> 1;
        for (int d = tid; d < DHIST; d += 1024)
            if (g_cumD[d] <= half && half < g_cumD[d + 1]) { s_dstar = d; s_r = half - g_cumD[d]; }
        __syncthreads();
        int dstar = s_dstar, r = s_r;
        for (int i = tid; i < NS; i += 1024)
            g_prod[i] = (i < L && g_deg[i] == dstar) ? 1 : 0;
        __syncthreads();
        sbScanFast<5>(g_prod, g_tieEx, N);
        __syncthreads();
        for (int i = tid; i < N; i += 1024) {
            int kp = 1;
            if (i < L) {
                int d = g_deg[i];
                if (d < dstar) kp = 0;
                else if (d == dstar && g_tieEx[i] < r) kp = 0;
            }
            g_keep[i] = kp;
        }
    }
    gridBar(++ep, nb);

    // ph13a: per-tile kept counts (tile = 4096 elems)
    for (int tile = bid; tile < NT2; tile += nb) {
        int t0 = tile * 4096 + tid * 4;
        int4 A = ((const int4*)g_triS0)[t0 >> 2];
        int4 B = ((const int4*)g_triS1)[t0 >> 2];
        int4 C = ((const int4*)g_triS2)[t0 >> 2];
        int av[4] = {A.x, A.y, A.z, A.w};
        int bv[4] = {B.x, B.y, B.z, B.w};
        int cv[4] = {C.x, C.y, C.z, C.w};
        int s = 0;
#pragma unroll
        for (int j = 0; j < 4; j++)
            if (t0 + j < T) s += g_keep[av[j]] & g_keep[bv[j]] & g_keep[cv[j]];
        int tot;
        blockScanEx(s, &tot);
        if (tid == 0) g_tileSum[tile] = tot;
    }
    gridBar(++ep, nb);

    // ph13b: scan tile sums (block 0)
    if (bid == 0) {
        int v = (tid < NT2) ? g_tileSum[tid] : 0;
        int tot, ex = blockScanEx(v, &tot);
        if (tid < NT2) g_tileOff[tid] = ex;
        if (tid == 0) { g_tileOff[NT2] = tot; g_P = tot; }
    }
    gridBar(++ep, nb);

    // ph13c: compact kept triplets (order-preserving) + present flags
    for (int tile = bid; tile < NT2; tile += nb) {
        int t0 = tile * 4096 + tid * 4;
        int4 A = ((const int4*)g_triS0)[t0 >> 2];
        int4 B = ((const int4*)g_triS1)[t0 >> 2];
        int4 C = ((const int4*)g_triS2)[t0 >> 2];
        int av[4] = {A.x, A.y, A.z, A.w};
        int bv[4] = {B.x, B.y, B.z, B.w};
        int cv[4] = {C.x, C.y, C.z, C.w};
        int m[4], s = 0;
#pragma unroll
        for (int j = 0; j < 4; j++) {
            m[j] = 0;
            if (t0 + j < T) m[j] = g_keep[av[j]] & g_keep[bv[j]] & g_keep[cv[j]];
            s += m[j];
        }
        int tot, ex = blockScanEx(s, &tot);
        int o = g_tileOff[tile] + ex;
#pragma unroll
        for (int j = 0; j < 4; j++) {
            if (m[j]) {
                g_tri0[o] = av[j]; g_tri1[o] = bv[j]; g_tri2[o] = cv[j];
                g_srcPresent[av[j]] = 1;
                g_present[av[j]] = 1; g_present[bv[j]] = 1; g_present[cv[j]] = 1;
                o++;
            }
        }
    }
    gridBar(++ep, nb);

    // ph14: rank scans (block 0)
    if (bid == 0) {
        sbScanFast<5>(g_srcPresent, g_srcRank, N);
        sbScanFast<5>(g_present, g_rank, N);
        if (tid == 0) g_segHead[g_srcRank[N]] = g_P;
    }
    gridBar(++ep, nb);

    int P = g_P;
    int U = g_srcRank[N];

    // ph15: new_ei output + segment heads
    for (int p = g0; p < P; p += gsz) {
        int a = g_tri0[p];
        int base = 64 * U;
        out[base + p]         = (float)g_rank[a];
        out[base + P + p]     = (float)g_rank[g_tri1[p]];
        out[base + 2 * P + p] = (float)g_rank[g_tri2[p]];
        if (p == 0 || g_tri0[p - 1] != a) g_segHead[g_srcRank[a]] = p;
    }
    gridBar(++ep, nb);

    // ph16: segment-mean + fused 3-tap matvec
    {
        int w = tid >> 5;
        for (int u = warpId; u < U; u += nwarps) {
            int h0 = g_segHead[u], h1 = g_segHead[u + 1];
            int a = g_tri0[h0];
            float sB0 = 0.f, sB1 = 0.f, sC0 = 0.f, sC1 = 0.f;
            for (int p = h0; p < h1; p++) {
                const float* xb = x + g_tri1[p] * 64;
                const float* xc = x + g_tri2[p] * 64;
                sB0 += xb[lane]; sB1 += xb[lane + 32];
                sC0 += xc[lane]; sC1 += xc[lane + 32];
            }
            float inv = 1.0f / (float)(h1 - h0);
            sv[w][lane] = x[a * 64 + lane];
            sv[w][lane + 32] = x[a * 64 + lane + 32];
            sv[w][64 + lane] = sB0 * inv;
            sv[w][64 + lane + 32] = sB1 * inv;
            sv[w][128 + lane] = sC0 * inv;
            sv[w][128 + lane + 32] = sC1 * inv;
            __syncwarp();
            float acc0 = bvec[lane], acc1 = bvec[lane + 32];
#pragma unroll 8
            for (int i = 0; i < 64; i++) {
                float v0 = sv[w][i], v1 = sv[w][64 + i], v2 = sv[w][128 + i];
                int base = i * 64 + lane;
                acc0 += g_Wt[base] * v0 + g_Wt[4096 + base] * v1 + g_Wt[8192 + base] * v2;
                acc1 += g_Wt[base + 32] * v0 + g_Wt[4096 + base + 32] * v1 + g_Wt[8192 + base + 32] * v2;
            }
            out[u * 64 + lane] = acc0;
            out[u * 64 + lane + 32] = acc1;
            __syncwarp();
        }
    }
}

extern "C" void kernel_launch(void* const* d_in, const int* in_sizes, int n_in,
                              void* d_out, int out_size) {
    const float* x = (const float*)d_in[0];
    const int* ei = (const int*)d_in[1];
    const float* W = (const float*)d_in[2];
    const float* b = (const float*)d_in[3];
    float* out = (float*)d_out;
    int N = in_sizes[0] / 64;
    int E = in_sizes[1] / 2;

    int dev = 0, sms = 148;
    cudaGetDevice(&dev);
    cudaDeviceGetAttribute(&sms, cudaDevAttrMultiProcessorCount, dev);

    kBarInit<<<1, 32>>>();
    kMega<<<sms, 1024>>>(x, ei, W, b, out, N, E);
}

// round 6
// speedup vs baseline: 1.0947x; 1.0947x over previous
#include <cuda_runtime.h>

#define NS 20480
#define EMAX 120000
#define TMAX 2097152
#define DHIST 16384
#define NT 512            /* TMAX/4096 lookback tiles */

__device__ __align__(16) int g_srcHist[NS + 8], g_tgtHist[NS + 8];
__device__ __align__(16) int g_srcBase[NS + 8], g_tgtBase[NS + 8];
__device__ int g_curA[NS + 8], g_curB[NS + 8], g_curC[NS + 8];
__device__ int g_eScat[EMAX], g_ePerm[EMAX];
__device__ int g_srcS[EMAX], g_tgtS[EMAX];
__device__ int g_oScat[EMAX], g_order[EMAX], g_hitA[EMAX];
__device__ __align__(16) int g_prod[NS + 8], g_prefixG[NS + 8];
__device__ int g_tri0[TMAX], g_tri1[TMAX], g_tri2[TMAX];
__device__ __align__(16) int g_triS0[TMAX], g_triS1[TMAX], g_triS2[TMAX];
__device__ int g_tScat[TMAX], g_tPerm[TMAX];
__device__ __align__(16) int g_histTri[NS + 8];
__device__ int g_triBase[NS + 8];
__device__ __align__(16) int g_deg[NS + 8];
__device__ int g_deg2[NS + 8];
__device__ __align__(16) int g_histD[DHIST + 8];
__device__ int g_cumD[DHIST + 8];
__device__ int g_maxNode, g_P;
__device__ __align__(16) int g_tieEx[NS + 8];
__device__ int g_keep[NS + 8];
__device__ __align__(16) int g_srcPresent[NS + 8], g_present[NS + 8];
__device__ int g_srcRank[NS + 8], g_rank[NS + 8];
__device__ int g_segHead[NS + 8];
__device__ float g_Wt[3 * 64 * 64];
__device__ volatile unsigned long long g_tileState[NT + 8];
__device__ unsigned long long g_barCount, g_barPhase;

__device__ __forceinline__ void gridBar(unsigned long long ep, int nb) {
    __syncthreads();
    if (threadIdx.x == 0) {
        __threadfence();
        unsigned long long old = atomicAdd(&g_barCount, 1ull);
        if (old == (unsigned long long)(nb - 1)) {
            g_barCount = 0ull;
            __threadfence();
            atomicExch(&g_barPhase, ep);
        } else {
            while (*(volatile unsigned long long*)&g_barPhase < ep) __nanosleep(64);
        }
        __threadfence();
    }
    __syncthreads();
}

__device__ __forceinline__ int blockScanEx(int v, int* tot) {
    __shared__ int s_w[32];
    __shared__ int s_tot;
    int lane = threadIdx.x & 31, wid = threadIdx.x >> 5, nw = blockDim.x >> 5;
    int inc = v;
#pragma unroll
    for (int o = 1; o < 32; o <<= 1) {
        int u = __shfl_up_sync(0xffffffffu, inc, o);
        if (lane >= o) inc += u;
    }
    if (lane == 31) s_w[wid] = inc;
    __syncthreads();
    if (wid == 0) {
        int sv2 = (lane < nw) ? s_w[lane] : 0;
        int si = sv2;
#pragma unroll
        for (int o = 1; o < 32; o <<= 1) {
            int u = __shfl_up_sync(0xffffffffu, si, o);
            if (lane >= o) si += u;
        }
        s_w[lane] = si - sv2;
        if (lane == 31) s_tot = si;
    }
    __syncthreads();
    int ex = inc - v + s_w[wid];
    *tot = s_tot;
    __syncthreads();
    return ex;
}

template <int VPT4>
__device__ void sbScanFast(const int* in, int* out, int n) {
    int v[VPT4 * 4];
    const int4* in4 = (const int4*)in;
#pragma unroll
    for (int j = 0; j < VPT4; j++) {
        int4 q = in4[threadIdx.x * VPT4 + j];
        v[4 * j] = q.x; v[4 * j + 1] = q.y; v[4 * j + 2] = q.z; v[4 * j + 3] = q.w;
    }
    int loc = 0;
#pragma unroll
    for (int j = 0; j < VPT4 * 4; j++) { int t = v[j]; v[j] = loc; loc += t; }
    int tot, ex = blockScanEx(loc, &tot);
    int base = threadIdx.x * VPT4 * 4;
#pragma unroll
    for (int j = 0; j < VPT4 * 4; j++) {
        int i = base + j;
        if (i < n) out[i] = ex + v[j];
    }
    if (threadIdx.x == 0) out[n] = tot;
}

__global__ void kBarInit() { g_barCount = 0ull; g_barPhase = 0ull; }

__global__ void __launch_bounds__(1024, 1) kMega(
    const float* __restrict__ x, const int* __restrict__ ei,
    const float* __restrict__ W, const float* __restrict__ bvec,
    float* __restrict__ out, int N, int E)
{
    __shared__ float sv[32][192];
    __shared__ int s_red[32];
    __shared__ int s_dstar, s_r, s_exTile;
    const int tid = threadIdx.x, bid = blockIdx.x, nb = gridDim.x;
    const int gsz = nb * 1024;
    const int g0 = bid * 1024 + tid;
    const int warpId = g0 >> 5, lane = tid & 31, nwarps = nb * 32;
    unsigned long long ep = 0;

    // ---- ph0: init ----
    for (int i = g0; i < NS; i += gsz) {
        g_srcHist[i] = 0; g_tgtHist[i] = 0; g_histTri[i] = 0; g_deg2[i] = 0;
        g_srcPresent[i] = 0; g_present[i] = 0;
        g_curA[i] = 0; g_curB[i] = 0; g_curC[i] = 0;
    }
    for (int i = g0; i < DHIST; i += gsz) g_histD[i] = 0;
    for (int i = g0; i <= NT; i += gsz) g_tileState[i] = 0ull;
    for (int i = g0; i < 12288; i += gsz) {
        int o = i & 63, ii = (i >> 6) & 63, k = i >> 12;
        g_Wt[i] = W[o * 192 + ii * 3 + k];
    }
    if (g0 == 0) g_maxNode = -1;
    gridBar(++ep, nb);

    // ---- ph1: edge histograms ----
    for (int e = g0; e < E; e += gsz) {
        atomicAdd(&g_srcHist[ei[e]], 1);
        atomicAdd(&g_tgtHist[ei[E + e]], 1);
    }
    gridBar(++ep, nb);

    // ---- ph2: base scans (block 0) ----
    if (bid == 0) {
        for (int i = tid; i < NS; i += 1024)
            g_prod[i] = (i < N) ? g_srcHist[i] * g_tgtHist[i] : 0;
        __syncthreads();
        sbScanFast<5>(g_srcHist, g_srcBase, N);
        sbScanFast<5>(g_tgtHist, g_tgtBase, N);
        sbScanFast<5>(g_prod, g_prefixG, N);
    }
    gridBar(++ep, nb);

    // ---- ph3: scatter by src + analytic degree partials (spread-address REDs) ----
    for (int e = g0; e < E; e += gsz) {
        int s = ei[e], t = ei[E + e];
        g_eScat[g_srcBase[s] + atomicAdd(&g_curA[s], 1)] = e;
        atomicAdd(&g_histTri[s], g_srcHist[t]);   // Σ outdeg(tgt(h)) over h with src=s
        atomicAdd(&g_deg2[t], g_tgtHist[s]);      // Σ indeg(src(e)) over e with tgt=t
    }
    gridBar(++ep, nb);

    // ---- ph4: finalize deg + maxNode (block-reduced), then src-bucket stable sort ----
    {
        int mloc = -1;
        for (int i = g0; i < NS; i += gsz) {
            int d = g_histTri[i] + g_srcHist[i] * g_tgtHist[i] + g_deg2[i];
            g_deg[i] = d;
            if (d > 0 && i > mloc) mloc = i;
        }
#pragma unroll
        for (int o = 16; o; o >>= 1) {
            int u = __shfl_down_sync(0xffffffffu, mloc, o);
            if (u > mloc) mloc = u;
        }
        if (lane == 0) s_red[tid >> 5] = mloc;
        __syncthreads();
        if (tid < 32) {
            int m = s_red[tid];
#pragma unroll
            for (int o = 16; o; o >>= 1) {
                int u = __shfl_down_sync(0xffffffffu, m, o);
                if (u > m) m = u;
            }
            if (tid == 0 && m >= 0) atomicMax(&g_maxNode, m);
        }
        __syncthreads();
    }
    for (int w = warpId; w < N; w += nwarps) {
        int lo = g_srcBase[w], s = g_srcBase[w + 1] - lo;
        for (int i = lane; i < s; i += 32) {
            int val = g_eScat[lo + i], r = 0;
            for (int j = 0; j < s; j++) r += (g_eScat[lo + j] < val);
            g_ePerm[lo + r] = val;
        }
        __syncwarp();
        for (int i = lane; i < s; i += 32) {
            int e = g_ePerm[lo + i];
            g_srcS[lo + i] = w;
            g_tgtS[lo + i] = ei[E + e];
        }
        __syncwarp();
    }
    gridBar(++ep, nb);

    // ---- ph5: (b0: scan histTri) ; all: scatter by tgt + degree histogram ----
    if (bid == 0) sbScanFast<5>(g_histTri, g_triBase, N);
    for (int j = g0; j < E; j += gsz) {
        int w = g_tgtS[j];
        g_oScat[g_tgtBase[w] + atomicAdd(&g_curB[w], 1)] = j;
    }
    {
        int L = g_maxNode + 1;
        for (int i = g0; i < L; i += gsz) {
            int d = g_deg[i];
            if (d > DHIST - 1) d = DHIST - 1;
            atomicAdd(&g_histD[d], 1);
        }
    }
    gridBar(++ep, nb);

    // ---- ph6: (b0: median select + keep) ; all: tgt-bucket sort + hitA ----
    if (bid == 0) {
        sbScanFast<4>(g_histD, g_cumD, DHIST);
        __syncthreads();
        int L = g_maxNode + 1, half = L >> 1;
        for (int d = tid; d < DHIST; d += 1024)
            if (g_cumD[d] <= half && half < g_cumD[d + 1]) { s_dstar = d; s_r = half - g_cumD[d]; }
        __syncthreads();
        int dstar = s_dstar, r = s_r;
        for (int i = tid; i < NS; i += 1024)
            g_prod[i] = (i < L && g_deg[i] == dstar) ? 1 : 0;
        __syncthreads();
        sbScanFast<5>(g_prod, g_tieEx, N);
        __syncthreads();
        for (int i = tid; i < N; i += 1024) {
            int kp = 1;
            if (i < L) {
                int d = g_deg[i];
                if (d < dstar) kp = 0;
                else if (d == dstar && g_tieEx[i] < r) kp = 0;
            }
            g_keep[i] = kp;
        }
    }
    for (int w = warpId; w < N; w += nwarps) {
        int lo = g_tgtBase[w], s = g_tgtBase[w + 1] - lo;
        for (int i = lane; i < s; i += 32) {
            int val = g_oScat[lo + i], r = 0;
            for (int j = 0; j < s; j++) r += (g_oScat[lo + j] < val);
            g_order[lo + r] = val;
        }
        __syncwarp();
        for (int i = lane; i < s; i += 32)
            g_hitA[lo + i] = g_srcS[g_order[lo + i]];
        __syncwarp();
    }
    gridBar(++ep, nb);

    // ---- ph7: generate triplets (pure stores, no atomics) ----
    for (int e = g0; e < E; e += gsz) {
        int v = g_srcS[e];
        int lb = g_tgtBase[v];
        int din = g_tgtBase[v + 1] - lb;
        if (din <= 0) continue;
        int t0 = g_prefixG[v] + (e - g_srcBase[v]) * din;
        int w = g_tgtS[e];
        for (int off = 0; off < din; off++) {
            int t = t0 + off;
            if (t >= TMAX) break;
            g_tri0[t] = g_hitA[lb + off];
            g_tri1[t] = v;
            g_tri2[t] = w;
        }
    }
    gridBar(++ep, nb);

    int T = g_prefixG[N]; if (T > TMAX) T = TMAX;

    // ---- ph8: scatter triplets by tri0 ----
    for (int t = g0; t < T; t += gsz) {
        int a = g_tri0[t];
        g_tScat[g_triBase[a] + atomicAdd(&g_curC[a], 1)] = t;
    }
    gridBar(++ep, nb);

    // ---- ph9: tri-bucket stable rank sort ----
    for (int w = warpId; w < N; w += nwarps) {
        int lo = g_triBase[w], s = g_triBase[w + 1] - lo;
        for (int i = lane; i < s; i += 32) {
            int val = g_tScat[lo + i], r = 0;
            for (int j = 0; j < s; j++) r += (g_tScat[lo + j] < val);
            g_tPerm[lo + r] = val;
        }
        __syncwarp();
        for (int i = lane; i < s; i += 32) {
            int t = g_tPerm[lo + i];
            g_triS0[lo + i] = g_tri0[t];
            g_triS1[lo + i] = g_tri1[t];
            g_triS2[lo + i] = g_tri2[t];
        }
        __syncwarp();
    }
    gridBar(++ep, nb);

    // ---- ph10: single-pass mask + order-preserving compaction (lookback) ----
    for (int tile = bid; tile < NT; tile += nb) {
        int t0 = tile * 4096 + tid * 4;
        int4 A = ((const int4*)g_triS0)[t0 >> 2];
        int4 B = ((const int4*)g_triS1)[t0 >> 2];
        int4 C = ((const int4*)g_triS2)[t0 >> 2];
        int av[4] = {A.x, A.y, A.z, A.w};
        int bv[4] = {B.x, B.y, B.z, B.w};
        int cv[4] = {C.x, C.y, C.z, C.w};
        int m[4], s = 0;
#pragma unroll
        for (int j = 0; j < 4; j++) {
            m[j] = 0;
            if (t0 + j < T) m[j] = g_keep[av[j]] & g_keep[bv[j]] & g_keep[cv[j]];
            s += m[j];
        }
        int tot, ex = blockScanEx(s, &tot);
        if (tid == 0) {
            if (tile == 0) {
                g_tileState[0] = (2ull << 32) | (unsigned)tot;
                s_exTile = 0;
                if (NT == 1) g_P = tot;
            } else {
                g_tileState[tile] = (1ull << 32) | (unsigned)tot;
                int exT = 0, p = tile - 1;
                while (true) {
                    unsigned long long st = g_tileState[p];
                    unsigned f = (unsigned)(st >> 32);
                    if (f == 0) { __nanosleep(32); continue; }
                    exT += (int)(st & 0xffffffffu);
                    if (f == 2) break;
                    p--;
                }
                s_exTile = exT;
                g_tileState[tile] = (2ull << 32) | (unsigned)(exT + tot);
                if (tile == NT - 1) g_P = exT + tot;
            }
        }
        __syncthreads();
        int o = s_exTile + ex;
#pragma unroll
        for (int j = 0; j < 4; j++) {
            if (m[j]) {
                g_tri0[o] = av[j]; g_tri1[o] = bv[j]; g_tri2[o] = cv[j];
                g_srcPresent[av[j]] = 1;
                g_present[av[j]] = 1; g_present[bv[j]] = 1; g_present[cv[j]] = 1;
                o++;
            }
        }
        __syncthreads();
    }
    gridBar(++ep, nb);

    // ---- ph11: rank scans (block 0) ----
    if (bid == 0) {
        sbScanFast<5>(g_srcPresent, g_srcRank, N);
        sbScanFast<5>(g_present, g_rank, N);
        if (tid == 0) g_segHead[g_srcRank[N]] = g_P;
    }
    gridBar(++ep, nb);

    int P = g_P;
    int U = g_srcRank[N];

    // ---- ph12: new_ei output + segment heads ----
    for (int p = g0; p < P; p += gsz) {
        int a = g_tri0[p];
        int base = 64 * U;
        out[base + p]         = (float)g_rank[a];
        out[base + P + p]     = (float)g_rank[g_tri1[p]];
        out[base + 2 * P + p] = (float)g_rank[g_tri2[p]];
        if (p == 0 || g_tri0[p - 1] != a) g_segHead[g_srcRank[a]] = p;
    }
    gridBar(++ep, nb);

    // ---- ph13: segment-mean + fused 3-tap matvec ----
    {
        int w = tid >> 5;
        for (int u = warpId; u < U; u += nwarps) {
            int h0 = g_segHead[u], h1 = g_segHead[u + 1];
            int a = g_tri0[h0];
            float sB0 = 0.f, sB1 = 0.f, sC0 = 0.f, sC1 = 0.f;
            for (int p = h0; p < h1; p++) {
                const float* xb = x + g_tri1[p] * 64;
                const float* xc = x + g_tri2[p] * 64;
                sB0 += xb[lane]; sB1 += xb[lane + 32];
                sC0 += xc[lane]; sC1 += xc[lane + 32];
            }
            float inv = 1.0f / (float)(h1 - h0);
            sv[w][lane] = x[a * 64 + lane];
            sv[w][lane + 32] = x[a * 64 + lane + 32];
            sv[w][64 + lane] = sB0 * inv;
            sv[w][64 + lane + 32] = sB1 * inv;
            sv[w][128 + lane] = sC0 * inv;
            sv[w][128 + lane + 32] = sC1 * inv;
            __syncwarp();
            float acc0 = bvec[lane], acc1 = bvec[lane + 32];
#pragma unroll 8
            for (int i = 0; i < 64; i++) {
                float v0 = sv[w][i], v1 = sv[w][64 + i], v2 = sv[w][128 + i];
                int base = i * 64 + lane;
                acc0 += g_Wt[base] * v0 + g_Wt[4096 + base] * v1 + g_Wt[8192 + base] * v2;
                acc1 += g_Wt[base + 32] * v0 + g_Wt[4096 + base + 32] * v1 + g_Wt[8192 + base + 32] * v2;
            }
            out[u * 64 + lane] = acc0;
            out[u * 64 + lane + 32] = acc1;
            __syncwarp();
        }
    }
}

extern "C" void kernel_launch(void* const* d_in, const int* in_sizes, int n_in,
                              void* d_out, int out_size) {
    const float* x = (const float*)d_in[0];
    const int* ei = (const int*)d_in[1];
    const float* W = (const float*)d_in[2];
    const float* b = (const float*)d_in[3];
    float* out = (float*)d_out;
    int N = in_sizes[0] / 64;
    int E = in_sizes[1] / 2;

    int dev = 0, sms = 148;
    cudaGetDevice(&dev);
    cudaDeviceGetAttribute(&sms, cudaDevAttrMultiProcessorCount, dev);

    kBarInit<<<1, 32>>>();
    kMega<<<sms, 1024>>>(x, ei, W, b, out, N, E);
}

// round 7
// speedup vs baseline: 1.2615x; 1.1524x over previous
#include <cuda_runtime.h>

#define NS 20480
#define EMAX 120000
#define TMAX 2097152
#define DHIST 16384
#define NT 512            /* TMAX/4096 lookback tiles */
#define MAXB 160

__device__ __align__(16) int g_srcHist[NS + 8], g_tgtHist[NS + 8];
__device__ __align__(16) int g_srcBase[NS + 8], g_tgtBase[NS + 8];
__device__ int g_curA[NS + 8], g_curB[NS + 8], g_curC[NS + 8];
__device__ int g_eScat[EMAX], g_ePerm[EMAX];
__device__ int g_srcS[EMAX], g_tgtS[EMAX];
__device__ int g_oScat[EMAX], g_order[EMAX], g_hitA[EMAX];
__device__ __align__(16) int g_prod[NS + 8], g_prefixG[NS + 8];
__device__ unsigned int g_triVW[TMAX];              // (v<<16)|w in generation order
__device__ int g_tScat[TMAX];                       // t values per tri0 bucket
__device__ __align__(16) int g_triSA[TMAX];         // sorted: bucket a
__device__ __align__(16) unsigned int g_triSVW[TMAX];
__device__ int g_cA[TMAX];                          // compacted kept
__device__ unsigned int g_cVW[TMAX];
__device__ __align__(16) int g_histTri[NS + 8];
__device__ int g_triBase[NS + 8];
__device__ __align__(16) int g_deg[NS + 8];
__device__ int g_deg2[NS + 8];
__device__ __align__(16) int g_histD[DHIST + 8];
__device__ int g_cumD[DHIST + 8];
__device__ int g_maxNode, g_P;
__device__ __align__(16) int g_tieEx[NS + 8];
__device__ int g_keep[NS + 8];
__device__ __align__(16) int g_srcPresent[NS + 8], g_present[NS + 8];
__device__ int g_srcRank[NS + 8], g_rank[NS + 8];
__device__ int g_segHead[NS + 8];
__device__ float g_Wt[3 * 64 * 64];
__device__ volatile unsigned long long g_tileState[NT + 8];
__device__ volatile int g_arrive[MAXB * 32];        // per-block slot, 128B stride
__device__ volatile int g_barPhase;

// ---- distributed grid barrier: slot arrivals + block-0 checker ----
__device__ __forceinline__ void gridBar(int ep, int nb) {
    __syncthreads();
    if (blockIdx.x == 0) {
        if (threadIdx.x < 32) {
            int lane = threadIdx.x;
            if (lane == 0) { __threadfence(); g_arrive[0] = ep; }
            bool ok;
            do {
                ok = true;
                for (int s = lane; s < nb; s += 32)
                    if (g_arrive[s * 32] < ep) ok = false;
            } while (__ballot_sync(0xffffffffu, !ok));
            if (lane == 0) { __threadfence(); g_barPhase = ep; }
        }
    } else if (threadIdx.x == 0) {
        __threadfence();
        g_arrive[blockIdx.x * 32] = ep;
        while (g_barPhase < ep) __nanosleep(32);
        __threadfence();
    }
    __syncthreads();
}

__device__ __forceinline__ int blockScanEx(int v, int* tot) {
    __shared__ int s_w[32];
    __shared__ int s_tot;
    int lane = threadIdx.x & 31, wid = threadIdx.x >> 5, nw = blockDim.x >> 5;
    int inc = v;
#pragma unroll
    for (int o = 1; o < 32; o <<= 1) {
        int u = __shfl_up_sync(0xffffffffu, inc, o);
        if (lane >= o) inc += u;
    }
    if (lane == 31) s_w[wid] = inc;
    __syncthreads();
    if (wid == 0) {
        int sv2 = (lane < nw) ? s_w[lane] : 0;
        int si = sv2;
#pragma unroll
        for (int o = 1; o < 32; o <<= 1) {
            int u = __shfl_up_sync(0xffffffffu, si, o);
            if (lane >= o) si += u;
        }
        s_w[lane] = si - sv2;
        if (lane == 31) s_tot = si;
    }
    __syncthreads();
    int ex = inc - v + s_w[wid];
    *tot = s_tot;
    __syncthreads();
    return ex;
}

template <int VPT4>
__device__ void sbScanFast(const int* in, int* out, int n) {
    int v[VPT4 * 4];
    const int4* in4 = (const int4*)in;
#pragma unroll
    for (int j = 0; j < VPT4; j++) {
        int4 q = in4[threadIdx.x * VPT4 + j];
        v[4 * j] = q.x; v[4 * j + 1] = q.y; v[4 * j + 2] = q.z; v[4 * j + 3] = q.w;
    }
    int loc = 0;
#pragma unroll
    for (int j = 0; j < VPT4 * 4; j++) { int t = v[j]; v[j] = loc; loc += t; }
    int tot, ex = blockScanEx(loc, &tot);
    int base = threadIdx.x * VPT4 * 4;
#pragma unroll
    for (int j = 0; j < VPT4 * 4; j++) {
        int i = base + j;
        if (i < n) out[i] = ex + v[j];
    }
    if (threadIdx.x == 0) out[n] = tot;
}

__global__ void kBarInit() {
    int i = blockIdx.x * blockDim.x + threadIdx.x;
    if (i < MAXB * 32) g_arrive[i] = 0;
    if (i == 0) g_barPhase = 0;
}

__global__ void __launch_bounds__(1024, 1) kMega(
    const float* __restrict__ x, const int* __restrict__ ei,
    const float* __restrict__ W, const float* __restrict__ bvec,
    float* __restrict__ out, int N, int E)
{
    __shared__ float sv[32][192];
    __shared__ int s_red[32];
    __shared__ int s_dstar, s_r, s_exTile;
    const int tid = threadIdx.x, bid = blockIdx.x, nb = gridDim.x;
    const int gsz = nb * 1024;
    const int g0 = bid * 1024 + tid;
    const int lane = tid & 31;
    const int warpId = g0 >> 5, nwarps = nb * 32;
    // partitions for phases where block 0 is busy scanning:
    const int e1 = (bid - 1) * 1024 + tid, s1 = (nb - 1) * 1024;
    const int warpId1 = ((bid - 1) * 1024 + tid) >> 5, nwarps1 = (nb - 1) * 32;
    int ep = 0;

    // ---- ph0: init ----
    for (int i = g0; i < NS; i += gsz) {
        g_srcHist[i] = 0; g_tgtHist[i] = 0; g_histTri[i] = 0; g_deg2[i] = 0;
        g_srcPresent[i] = 0; g_present[i] = 0;
        g_curA[i] = 0; g_curB[i] = 0; g_curC[i] = 0;
    }
    for (int i = g0; i < DHIST; i += gsz) g_histD[i] = 0;
    for (int i = g0; i <= NT; i += gsz) g_tileState[i] = 0ull;
    for (int i = g0; i < 12288; i += gsz) {
        int o = i & 63, ii = (i >> 6) & 63, k = i >> 12;
        g_Wt[i] = W[o * 192 + ii * 3 + k];
    }
    if (g0 == 0) g_maxNode = -1;
    gridBar(++ep, nb);

    // ---- ph1: edge histograms ----
    for (int e = g0; e < E; e += gsz) {
        atomicAdd(&g_srcHist[ei[e]], 1);
        atomicAdd(&g_tgtHist[ei[E + e]], 1);
    }
    gridBar(++ep, nb);

    // ---- ph2: b0 scans srcBase ----
    if (bid == 0) sbScanFast<5>(g_srcHist, g_srcBase, N);
    gridBar(++ep, nb);

    // ---- ph3: blocks 1+: scatter by src + analytic degree partials.
    //          b0: scans tgtBase + prefixG ----
    if (bid == 0) {
        for (int i = tid; i < NS; i += 1024)
            g_prod[i] = (i < N) ? g_srcHist[i] * g_tgtHist[i] : 0;
        __syncthreads();
        sbScanFast<5>(g_tgtHist, g_tgtBase, N);
        sbScanFast<5>(g_prod, g_prefixG, N);
    } else {
        for (int e = e1; e < E; e += s1) {
            int s = ei[e], t = ei[E + e];
            g_eScat[g_srcBase[s] + atomicAdd(&g_curA[s], 1)] = e;
            atomicAdd(&g_histTri[s], g_srcHist[t]);
            atomicAdd(&g_deg2[t], g_tgtHist[s]);
        }
    }
    gridBar(++ep, nb);

    // ---- ph4: deg finalize + maxNode reduce, then src-bucket stable sort ----
    {
        int mloc = -1;
        for (int i = g0; i < NS; i += gsz) {
            int d = g_histTri[i] + g_srcHist[i] * g_tgtHist[i] + g_deg2[i];
            g_deg[i] = d;
            if (d > 0 && i > mloc) mloc = i;
        }
#pragma unroll
        for (int o = 16; o; o >>= 1) {
            int u = __shfl_down_sync(0xffffffffu, mloc, o);
            if (u > mloc) mloc = u;
        }
        if (lane == 0) s_red[tid >> 5] = mloc;
        __syncthreads();
        if (tid < 32) {
            int m = s_red[tid];
#pragma unroll
            for (int o = 16; o; o >>= 1) {
                int u = __shfl_down_sync(0xffffffffu, m, o);
                if (u > m) m = u;
            }
            if (tid == 0 && m >= 0) atomicMax(&g_maxNode, m);
        }
        __syncthreads();
    }
    for (int w = warpId; w < N; w += nwarps) {
        int lo = g_srcBase[w], s = g_srcBase[w + 1] - lo;
        for (int i = lane; i < s; i += 32) {
            int val = g_eScat[lo + i], r = 0;
            for (int j = 0; j < s; j++) r += (g_eScat[lo + j] < val);
            g_ePerm[lo + r] = val;
        }
        __syncwarp();
        for (int i = lane; i < s; i += 32) {
            int e = g_ePerm[lo + i];
            g_srcS[lo + i] = w;
            g_tgtS[lo + i] = ei[E + e];
        }
        __syncwarp();
    }
    gridBar(++ep, nb);

    // ---- ph5: blocks 1+: scatter by tgt + degree histogram.  b0: scan histTri ----
    if (bid == 0) {
        sbScanFast<5>(g_histTri, g_triBase, N);
    } else {
        for (int j = e1; j < E; j += s1) {
            int w = g_tgtS[j];
            g_oScat[g_tgtBase[w] + atomicAdd(&g_curB[w], 1)] = j;
        }
        int L = g_maxNode + 1;
        for (int i = e1; i < L; i += s1) {
            int d = g_deg[i];
            if (d > DHIST - 1) d = DHIST - 1;
            atomicAdd(&g_histD[d], 1);
        }
    }
    gridBar(++ep, nb);

    // ---- ph6: blocks 1+: tgt-bucket sort + hitA.  b0: median select + keep ----
    if (bid == 0) {
        sbScanFast<4>(g_histD, g_cumD, DHIST);
        __syncthreads();
        int L = g_maxNode + 1, half = L >> 1;
        for (int d = tid; d < DHIST; d += 1024)
            if (g_cumD[d] <= half && half < g_cumD[d + 1]) { s_dstar = d; s_r = half - g_cumD[d]; }
        __syncthreads();
        int dstar = s_dstar, r = s_r;
        for (int i = tid; i < NS; i += 1024)
            g_prod[i] = (i < L && g_deg[i] == dstar) ? 1 : 0;
        __syncthreads();
        sbScanFast<5>(g_prod, g_tieEx, N);
        __syncthreads();
        for (int i = tid; i < N; i += 1024) {
            int kp = 1;
            if (i < L) {
                int d = g_deg[i];
                if (d < dstar) kp = 0;
                else if (d == dstar && g_tieEx[i] < r) kp = 0;
            }
            g_keep[i] = kp;
        }
    } else {
        for (int w = warpId1; w < N; w += nwarps1) {
            int lo = g_tgtBase[w], s = g_tgtBase[w + 1] - lo;
            for (int i = lane; i < s; i += 32) {
                int val = g_oScat[lo + i], r = 0;
                for (int j = 0; j < s; j++) r += (g_oScat[lo + j] < val);
                g_order[lo + r] = val;
            }
            __syncwarp();
            for (int i = lane; i < s; i += 32)
                g_hitA[lo + i] = g_srcS[g_order[lo + i]];
            __syncwarp();
        }
    }
    gridBar(++ep, nb);

    // ---- ph7: generate (packed) + scatter into tri0 buckets + present flags ----
    for (int e = g0; e < E; e += gsz) {
        int v = g_srcS[e];
        int lb = g_tgtBase[v];
        int din = g_tgtBase[v + 1] - lb;
        if (din <= 0) continue;
        int t0 = g_prefixG[v] + (e - g_srcBase[v]) * din;
        int w = g_tgtS[e];
        unsigned vw = ((unsigned)v << 16) | (unsigned)w;
        int kvw = g_keep[v] & g_keep[w];
        for (int off = 0; off < din; off++) {
            int t = t0 + off;
            if (t >= TMAX) break;
            int a = g_hitA[lb + off];
            g_triVW[t] = vw;
            g_tScat[g_triBase[a] + atomicAdd(&g_curC[a], 1)] = t;
            if (kvw & g_keep[a]) {
                g_srcPresent[a] = 1;
                g_present[a] = 1; g_present[v] = 1; g_present[w] = 1;
            }
        }
    }
    gridBar(++ep, nb);

    int T = g_prefixG[N]; if (T > TMAX) T = TMAX;

    // ---- ph8: blocks 1+: tri-bucket stable rank sort (one pass, direct gather).
    //          b0: rank scans ----
    if (bid == 0) {
        sbScanFast<5>(g_srcPresent, g_srcRank, N);
        sbScanFast<5>(g_present, g_rank, N);
    } else {
        for (int w = warpId1; w < N; w += nwarps1) {
            int lo = g_triBase[w], s = g_triBase[w + 1] - lo;
            for (int i = lane; i < s; i += 32) {
                int val = g_tScat[lo + i], r = 0;
                for (int j = 0; j < s; j++) r += (g_tScat[lo + j] < val);
                g_triSA[lo + r] = w;
                g_triSVW[lo + r] = g_triVW[val];
            }
            __syncwarp();
        }
    }
    gridBar(++ep, nb);

    // ---- ph9: single-pass mask + order-preserving compaction (lookback) ----
    for (int tile = bid; tile < NT; tile += nb) {
        int t0 = tile * 4096 + tid * 4;
        int4 A = ((const int4*)g_triSA)[t0 >> 2];
        uint4 V = ((const uint4*)g_triSVW)[t0 >> 2];
        int av[4] = {A.x, A.y, A.z, A.w};
        unsigned vv[4] = {V.x, V.y, V.z, V.w};
        int m[4], s = 0;
#pragma unroll
        for (int j = 0; j < 4; j++) {
            m[j] = 0;
            if (t0 + j < T)
                m[j] = g_keep[av[j]] & g_keep[vv[j] >> 16] & g_keep[vv[j] & 0xffffu];
            s += m[j];
        }
        int tot, ex = blockScanEx(s, &tot);
        if (tid == 0) {
            if (tile == 0) {
                g_tileState[0] = (2ull << 32) | (unsigned)tot;
                s_exTile = 0;
            } else {
                g_tileState[tile] = (1ull << 32) | (unsigned)tot;
                int exT = 0, p = tile - 1;
                while (true) {
                    unsigned long long st = g_tileState[p];
                    unsigned f = (unsigned)(st >> 32);
                    if (f == 0) { __nanosleep(32); continue; }
                    exT += (int)(st & 0xffffffffu);
                    if (f == 2) break;
                    p--;
                }
                s_exTile = exT;
                g_tileState[tile] = (2ull << 32) | (unsigned)(exT + tot);
            }
            if (tile == NT - 1) g_P = s_exTile + tot;
        }
        __syncthreads();
        int o = s_exTile + ex;
#pragma unroll
        for (int j = 0; j < 4; j++) {
            if (m[j]) { g_cA[o] = av[j]; g_cVW[o] = vv[j]; o++; }
        }
        __syncthreads();
    }
    gridBar(++ep, nb);

    int P = g_P;
    int U = g_srcRank[N];

    // ---- ph10: new_ei output + segment heads ----
    if (g0 == 0) g_segHead[U] = P;
    for (int p = g0; p < P; p += gsz) {
        int a = g_cA[p];
        unsigned vw = g_cVW[p];
        int base = 64 * U;
        out[base + p]         = (float)g_rank[a];
        out[base + P + p]     = (float)g_rank[vw >> 16];
        out[base + 2 * P + p] = (float)g_rank[vw & 0xffffu];
        if (p == 0 || g_cA[p - 1] != a) g_segHead[g_srcRank[a]] = p;
    }
    gridBar(++ep, nb);

    // ---- ph11: segment-mean + fused 3-tap matvec ----
    {
        int w = tid >> 5;
        for (int u = warpId; u < U; u += nwarps) {
            int h0 = g_segHead[u], h1 = g_segHead[u + 1];
            int a = g_cA[h0];
            float sB0 = 0.f, sB1 = 0.f, sC0 = 0.f, sC1 = 0.f;
            for (int p = h0; p < h1; p++) {
                unsigned vw = g_cVW[p];
                const float* xb = x + (vw >> 16) * 64;
                const float* xc = x + (vw & 0xffffu) * 64;
                sB0 += xb[lane]; sB1 += xb[lane + 32];
                sC0 += xc[lane]; sC1 += xc[lane + 32];
            }
            float inv = 1.0f / (float)(h1 - h0);
            sv[w][lane] = x[a * 64 + lane];
            sv[w][lane + 32] = x[a * 64 + lane + 32];
            sv[w][64 + lane] = sB0 * inv;
            sv[w][64 + lane + 32] = sB1 * inv;
            sv[w][128 + lane] = sC0 * inv;
            sv[w][128 + lane + 32] = sC1 * inv;
            __syncwarp();
            float acc0 = bvec[lane], acc1 = bvec[lane + 32];
#pragma unroll 8
            for (int i = 0; i < 64; i++) {
                float v0 = sv[w][i], v1 = sv[w][64 + i], v2 = sv[w][128 + i];
                int base = i * 64 + lane;
                acc0 += g_Wt[base] * v0 + g_Wt[4096 + base] * v1 + g_Wt[8192 + base] * v2;
                acc1 += g_Wt[base + 32] * v0 + g_Wt[4096 + base + 32] * v1 + g_Wt[8192 + base + 32] * v2;
            }
            out[u * 64 + lane] = acc0;
            out[u * 64 + lane + 32] = acc1;
            __syncwarp();
        }
    }
}

extern "C" void kernel_launch(void* const* d_in, const int* in_sizes, int n_in,
                              void* d_out, int out_size) {
    const float* x = (const float*)d_in[0];
    const int* ei = (const int*)d_in[1];
    const float* W = (const float*)d_in[2];
    const float* b = (const float*)d_in[3];
    float* out = (float*)d_out;
    int N = in_sizes[0] / 64;
    int E = in_sizes[1] / 2;

    int dev = 0, sms = 148;
    cudaGetDevice(&dev);
    cudaDeviceGetAttribute(&sms, cudaDevAttrMultiProcessorCount, dev);
    if (sms > MAXB) sms = MAXB;

    kBarInit<<<20, 256>>>();
    kMega<<<sms, 1024>>>(x, ei, W, b, out, N, E);
}

// round 8
// speedup vs baseline: 1.5490x; 1.2279x over previous
#include <cuda_runtime.h>

#define NS 20480
#define EMAX 120000
#define TMAX 2097152
#define DHIST 16384
#define NT 512            /* TMAX/4096 lookback tiles */
#define MAXB 160
#define DAMAX 64          /* max src-bucket size handled by gen sort */

__device__ __align__(16) int g_srcHist[NS + 8], g_tgtHist[NS + 8];
__device__ __align__(16) int g_srcBase[NS + 8];
__device__ int g_curA[NS + 8];
__device__ int g_eScat[EMAX], g_ePerm[EMAX];
__device__ int g_tgtS[EMAX];
__device__ __align__(16) int g_prod[NS + 8];
__device__ __align__(16) int g_triSA[TMAX];          // sorted bucket id a
__device__ __align__(16) unsigned int g_triSVW[TMAX];// (v<<16)|w
__device__ int g_cA[TMAX];                           // compacted kept
__device__ unsigned int g_cVW[TMAX];
__device__ __align__(16) int g_histTri[NS + 8];
__device__ int g_triBase[NS + 8];
__device__ __align__(16) int g_deg[NS + 8];
__device__ int g_deg2[NS + 8];
__device__ __align__(16) int g_histD[DHIST + 8];
__device__ int g_cumD[DHIST + 8];
__device__ int g_maxNode, g_P;
__device__ __align__(16) int g_tieEx[NS + 8];
__device__ int g_keep[NS + 8];
__device__ __align__(16) int g_srcPresent[NS + 8], g_present[NS + 8];
__device__ int g_srcRank[NS + 8], g_rank[NS + 8];
__device__ int g_segHead[NS + 8];
__device__ float g_Wt[3 * 64 * 64];
__device__ volatile unsigned long long g_tileState[NT + 8];
__device__ volatile int g_arrive[MAXB * 32];
__device__ volatile int g_barPhase;

// ---- distributed grid barrier: slot arrivals + block-0 checker ----
__device__ __forceinline__ void gridBar(int ep, int nb) {
    __syncthreads();
    if (blockIdx.x == 0) {
        if (threadIdx.x < 32) {
            int lane = threadIdx.x;
            if (lane == 0) { __threadfence(); g_arrive[0] = ep; }
            bool ok;
            do {
                ok = true;
                for (int s = lane; s < nb; s += 32)
                    if (g_arrive[s * 32] < ep) ok = false;
            } while (__ballot_sync(0xffffffffu, !ok));
            if (lane == 0) { __threadfence(); g_barPhase = ep; }
        }
    } else if (threadIdx.x == 0) {
        __threadfence();
        g_arrive[blockIdx.x * 32] = ep;
        while (g_barPhase < ep) __nanosleep(32);
        __threadfence();
    }
    __syncthreads();
}

__device__ __forceinline__ int blockScanEx(int v, int* tot) {
    __shared__ int s_w[32];
    __shared__ int s_tot;
    int lane = threadIdx.x & 31, wid = threadIdx.x >> 5, nw = blockDim.x >> 5;
    int inc = v;
#pragma unroll
    for (int o = 1; o < 32; o <<= 1) {
        int u = __shfl_up_sync(0xffffffffu, inc, o);
        if (lane >= o) inc += u;
    }
    if (lane == 31) s_w[wid] = inc;
    __syncthreads();
    if (wid == 0) {
        int sv2 = (lane < nw) ? s_w[lane] : 0;
        int si = sv2;
#pragma unroll
        for (int o = 1; o < 32; o <<= 1) {
            int u = __shfl_up_sync(0xffffffffu, si, o);
            if (lane >= o) si += u;
        }
        s_w[lane] = si - sv2;
        if (lane == 31) s_tot = si;
    }
    __syncthreads();
    int ex = inc - v + s_w[wid];
    *tot = s_tot;
    __syncthreads();
    return ex;
}

template <int VPT4>
__device__ void sbScanFast(const int* in, int* out, int n) {
    int v[VPT4 * 4];
    const int4* in4 = (const int4*)in;
#pragma unroll
    for (int j = 0; j < VPT4; j++) {
        int4 q = in4[threadIdx.x * VPT4 + j];
        v[4 * j] = q.x; v[4 * j + 1] = q.y; v[4 * j + 2] = q.z; v[4 * j + 3] = q.w;
    }
    int loc = 0;
#pragma unroll
    for (int j = 0; j < VPT4 * 4; j++) { int t = v[j]; v[j] = loc; loc += t; }
    int tot, ex = blockScanEx(loc, &tot);
    int base = threadIdx.x * VPT4 * 4;
#pragma unroll
    for (int j = 0; j < VPT4 * 4; j++) {
        int i = base + j;
        if (i < n) out[i] = ex + v[j];
    }
    if (threadIdx.x == 0) out[n] = tot;
}

__global__ void kBarInit() {
    int i = blockIdx.x * blockDim.x + threadIdx.x;
    if (i < MAXB * 32) g_arrive[i] = 0;
    if (i == 0) g_barPhase = 0;
}

__global__ void __launch_bounds__(1024, 1) kMega(
    const float* __restrict__ x, const int* __restrict__ ei,
    const float* __restrict__ W, const float* __restrict__ bvec,
    float* __restrict__ out, int N, int E)
{
    __shared__ float sv[32][192];
    __shared__ int s_uns[32][DAMAX];
    __shared__ int s_srt[32][DAMAX];
    __shared__ int s_red[32];
    __shared__ int s_dstar, s_r, s_exTile;
    const int tid = threadIdx.x, bid = blockIdx.x, nb = gridDim.x;
    const int gsz = nb * 1024;
    const int g0 = bid * 1024 + tid;
    const int lane = tid & 31, w = tid >> 5;
    const int warpId = g0 >> 5, nwarps = nb * 32;
    const int warpId1 = ((bid - 1) * 1024 + tid) >> 5, nwarps1 = (nb - 1) * 32;
    int ep = 0;

    // ---- ph0: init ----
    for (int i = g0; i < NS; i += gsz) {
        g_srcHist[i] = 0; g_tgtHist[i] = 0; g_histTri[i] = 0; g_deg2[i] = 0;
        g_srcPresent[i] = 0; g_present[i] = 0; g_curA[i] = 0;
    }
    for (int i = g0; i < DHIST; i += gsz) g_histD[i] = 0;
    for (int i = g0; i <= NT; i += gsz) g_tileState[i] = 0ull;
    for (int i = g0; i < 12288; i += gsz) {
        int o = i & 63, ii = (i >> 6) & 63, k = i >> 12;
        g_Wt[i] = W[o * 192 + ii * 3 + k];
    }
    if (g0 == 0) g_maxNode = -1;
    gridBar(++ep, nb);

    // ---- ph1: edge histograms ----
    for (int e = g0; e < E; e += gsz) {
        atomicAdd(&g_srcHist[ei[e]], 1);
        atomicAdd(&g_tgtHist[ei[E + e]], 1);
    }
    gridBar(++ep, nb);

    // ---- ph2: b0 scans srcBase ----
    if (bid == 0) sbScanFast<5>(g_srcHist, g_srcBase, N);
    gridBar(++ep, nb);

    // ---- ph3: scatter by src + analytic degree partials ----
    for (int e = g0; e < E; e += gsz) {
        int s = ei[e], t = ei[E + e];
        g_eScat[g_srcBase[s] + atomicAdd(&g_curA[s], 1)] = e;
        atomicAdd(&g_histTri[s], g_srcHist[t]);   // appearances as tri0
        atomicAdd(&g_deg2[t], g_tgtHist[s]);      // appearances as tri2
    }
    gridBar(++ep, nb);

    // ---- ph4: b0: scan triBase.  blocks 1+: deg finalize + maxNode + src sort ----
    if (bid == 0) {
        sbScanFast<5>(g_histTri, g_triBase, N);
    } else {
        int mloc = -1;
        for (int i = (bid - 1) * 1024 + tid; i < NS; i += (nb - 1) * 1024) {
            int d = g_histTri[i] + g_srcHist[i] * g_tgtHist[i] + g_deg2[i];
            g_deg[i] = d;
            if (d > 0 && i > mloc) mloc = i;
        }
#pragma unroll
        for (int o = 16; o; o >>= 1) {
            int u = __shfl_down_sync(0xffffffffu, mloc, o);
            if (u > mloc) mloc = u;
        }
        if (lane == 0) s_red[w] = mloc;
        __syncthreads();
        if (tid < 32) {
            int m = s_red[tid];
#pragma unroll
            for (int o = 16; o; o >>= 1) {
                int u = __shfl_down_sync(0xffffffffu, m, o);
                if (u > m) m = u;
            }
            if (tid == 0 && m >= 0) atomicMax(&g_maxNode, m);
        }
        __syncthreads();
        for (int v = warpId1; v < N; v += nwarps1) {
            int lo = g_srcBase[v], s = g_srcBase[v + 1] - lo;
            for (int i = lane; i < s; i += 32) {
                int val = g_eScat[lo + i], r = 0;
                for (int j = 0; j < s; j++) r += (g_eScat[lo + j] < val);
                g_ePerm[lo + r] = val;
            }
            __syncwarp();
            for (int i = lane; i < s; i += 32)
                g_tgtS[lo + i] = ei[E + g_ePerm[lo + i]];
            __syncwarp();
        }
    }
    gridBar(++ep, nb);

    // ---- ph5: degree histogram ----
    {
        int L = g_maxNode + 1;
        for (int i = g0; i < L; i += gsz) {
            int d = g_deg[i];
            if (d > DHIST - 1) d = DHIST - 1;
            atomicAdd(&g_histD[d], 1);
        }
    }
    gridBar(++ep, nb);

    // ---- ph6: b0: median select + keep.  blocks 1+: DIRECT SORTED GENERATION ----
    if (bid == 0) {
        sbScanFast<4>(g_histD, g_cumD, DHIST);
        __syncthreads();
        int L = g_maxNode + 1, half = L >> 1;
        for (int d = tid; d < DHIST; d += 1024)
            if (g_cumD[d] <= half && half < g_cumD[d + 1]) { s_dstar = d; s_r = half - g_cumD[d]; }
        __syncthreads();
        int dstar = s_dstar, r = s_r;
        for (int i = tid; i < NS; i += 1024)
            g_prod[i] = (i < L && g_deg[i] == dstar) ? 1 : 0;
        __syncthreads();
        sbScanFast<5>(g_prod, g_tieEx, N);
        __syncthreads();
        for (int i = tid; i < N; i += 1024) {
            int kp = 1;
            if (i < L) {
                int d = g_deg[i];
                if (d < dstar) kp = 0;
                else if (d == dstar && g_tieEx[i] < r) kp = 0;
            }
            g_keep[i] = kp;
        }
    } else {
        // per bucket a: sort a's out-edges by target (stable), then for each
        // target-group (v,k): for e in v's src-bucket ascending, emit k copies
        // of (a, v, tgt[e]) — exactly the reference's post-sort triplet order.
        for (int a = warpId1; a < N; a += nwarps1) {
            int lo = g_srcBase[a], da = g_srcBase[a + 1] - lo;
            if (da == 0) continue;
            int dc = da > DAMAX ? DAMAX : da;
            for (int i = lane; i < dc; i += 32) s_uns[w][i] = g_tgtS[lo + i];
            __syncwarp();
            for (int i = lane; i < dc; i += 32) {
                int vi = s_uns[w][i], r = 0;
                for (int j = 0; j < dc; j++) {
                    int vj = s_uns[w][j];
                    r += (vj < vi) | ((vj == vi) & (j < i));
                }
                s_srt[w][r] = vi;
            }
            __syncwarp();
            int p = g_triBase[a];
            int idx = 0;
            while (idx < dc) {
                int v = s_srt[w][idx];
                int k = 1;
                while (idx + k < dc && s_srt[w][idx + k] == v) k++;
                int eb = g_srcBase[v], din = g_srcBase[v + 1] - eb;
                int tot = k * din;
                unsigned vhi = (unsigned)v << 16;
                for (int j = lane; j < tot; j += 32) {
                    int e = eb + j / k;
                    g_triSA[p + j] = a;
                    g_triSVW[p + j] = vhi | (unsigned)g_tgtS[e];
                }
                p += tot;
                idx += k;
            }
            __syncwarp();
        }
    }
    gridBar(++ep, nb);

    int T = g_triBase[N]; if (T > TMAX) T = TMAX;

    // ---- ph7: single-pass mask + order-preserving compaction + present flags ----
    for (int tile = bid; tile < NT; tile += nb) {
        int t0 = tile * 4096 + tid * 4;
        int4 A = ((const int4*)g_triSA)[t0 >> 2];
        uint4 V = ((const uint4*)g_triSVW)[t0 >> 2];
        int av[4] = {A.x, A.y, A.z, A.w};
        unsigned vv[4] = {V.x, V.y, V.z, V.w};
        int m[4], s = 0;
#pragma unroll
        for (int j = 0; j < 4; j++) {
            m[j] = 0;
            if (t0 + j < T)
                m[j] = g_keep[av[j]] & g_keep[vv[j] >> 16] & g_keep[vv[j] & 0xffffu];
            s += m[j];
        }
        int tot, ex = blockScanEx(s, &tot);
        if (tid == 0) {
            if (tile == 0) {
                g_tileState[0] = (2ull << 32) | (unsigned)tot;
                s_exTile = 0;
            } else {
                g_tileState[tile] = (1ull << 32) | (unsigned)tot;
                int exT = 0, p = tile - 1;
                while (true) {
                    unsigned long long st = g_tileState[p];
                    unsigned f = (unsigned)(st >> 32);
                    if (f == 0) { __nanosleep(32); continue; }
                    exT += (int)(st & 0xffffffffu);
                    if (f == 2) break;
                    p--;
                }
                s_exTile = exT;
                g_tileState[tile] = (2ull << 32) | (unsigned)(exT + tot);
            }
            if (tile == NT - 1) g_P = s_exTile + tot;
        }
        __syncthreads();
        int o = s_exTile + ex;
#pragma unroll
        for (int j = 0; j < 4; j++) {
            if (m[j]) {
                g_cA[o] = av[j]; g_cVW[o] = vv[j]; o++;
                int v = vv[j] >> 16, ww = vv[j] & 0xffffu;
                g_srcPresent[av[j]] = 1;
                g_present[av[j]] = 1; g_present[v] = 1; g_present[ww] = 1;
            }
        }
        __syncthreads();
    }
    gridBar(++ep, nb);

    // ---- ph8: b0: rank scans ----
    if (bid == 0) {
        sbScanFast<5>(g_srcPresent, g_srcRank, N);
        sbScanFast<5>(g_present, g_rank, N);
    }
    gridBar(++ep, nb);

    int P = g_P;
    int U = g_srcRank[N];

    // ---- ph9: new_ei output + segment heads ----
    if (g0 == 0) g_segHead[U] = P;
    for (int p = g0; p < P; p += gsz) {
        int a = g_cA[p];
        unsigned vw = g_cVW[p];
        int base = 64 * U;
        out[base + p]         = (float)g_rank[a];
        out[base + P + p]     = (float)g_rank[vw >> 16];
        out[base + 2 * P + p] = (float)g_rank[vw & 0xffffu];
        if (p == 0 || g_cA[p - 1] != a) g_segHead[g_srcRank[a]] = p;
    }
    gridBar(++ep, nb);

    // ---- ph10: segment-mean + fused 3-tap matvec ----
    for (int u = warpId; u < U; u += nwarps) {
        int h0 = g_segHead[u], h1 = g_segHead[u + 1];
        int a = g_cA[h0];
        float sB0 = 0.f, sB1 = 0.f, sC0 = 0.f, sC1 = 0.f;
        for (int p = h0; p < h1; p++) {
            unsigned vw = g_cVW[p];
            const float* xb = x + (vw >> 16) * 64;
            const float* xc = x + (vw & 0xffffu) * 64;
            sB0 += xb[lane]; sB1 += xb[lane + 32];
            sC0 += xc[lane]; sC1 += xc[lane + 32];
        }
        float inv = 1.0f / (float)(h1 - h0);
        sv[w][lane] = x[a * 64 + lane];
        sv[w][lane + 32] = x[a * 64 + lane + 32];
        sv[w][64 + lane] = sB0 * inv;
        sv[w][64 + lane + 32] = sB1 * inv;
        sv[w][128 + lane] = sC0 * inv;
        sv[w][128 + lane + 32] = sC1 * inv;
        __syncwarp();
        float acc0 = bvec[lane], acc1 = bvec[lane + 32];
#pragma unroll 8
        for (int i = 0; i < 64; i++) {
            float v0 = sv[w][i], v1 = sv[w][64 + i], v2 = sv[w][128 + i];
            int base = i * 64 + lane;
            acc0 += g_Wt[base] * v0 + g_Wt[4096 + base] * v1 + g_Wt[8192 + base] * v2;
            acc1 += g_Wt[base + 32] * v0 + g_Wt[4096 + base + 32] * v1 + g_Wt[8192 + base + 32] * v2;
        }
        out[u * 64 + lane] = acc0;
        out[u * 64 + lane + 32] = acc1;
        __syncwarp();
    }
}

extern "C" void kernel_launch(void* const* d_in, const int* in_sizes, int n_in,
                              void* d_out, int out_size) {
    const float* x = (const float*)d_in[0];
    const int* ei = (const int*)d_in[1];
    const float* W = (const float*)d_in[2];
    const float* b = (const float*)d_in[3];
    float* out = (float*)d_out;
    int N = in_sizes[0] / 64;
    int E = in_sizes[1] / 2;

    int dev = 0, sms = 148;
    cudaGetDevice(&dev);
    cudaDeviceGetAttribute(&sms, cudaDevAttrMultiProcessorCount, dev);
    if (sms > MAXB) sms = MAXB;

    kBarInit<<<20, 256>>>();
    kMega<<<sms, 1024>>>(x, ei, W, b, out, N, E);
}